// round 14
// baseline (speedup 1.0000x reference)
#include <cuda_runtime.h>

// CostVolume: left,right [B,C,H,W] f32 -> out [B,2C,D,H,W] f32
//   out[b, c,      d, h, w] = (w+d < W) ? left [b,c,h,w+d] : 0
//   out[b, C + c,  d, h, w] = (w-d >= 0)? right[b,c,h,w-d] : 0
//
// Fixed shapes: B=2, C=32, H=128, W=256, D=32.
//
// R14: fusion-depth probe. Identical per-thread structure to the converged
// R6 kernel (20-float smem window -> one uninterrupted burst of 16 x
// STG.128 st.global.cs), but 1024-thread CTAs cover 4 adjacent h rows
// (grid 2048): one staging phase + one __syncthreads per 4 rows instead of
// per 2. Unlike the failed R5 4-row variant, no interleaved reloads — each
// thread still owns exactly one (row, half, dblock, column) and does one
// burst. Occ drops to ~50% (1 CTA/SM at 38 regs x 1024 thr), proven
// harmless by the 41-69% occupancy sweep (DRAM% flat).

namespace {
constexpr int B = 2;
constexpr int C = 32;
constexpr int H = 128;
constexpr int W = 256;
constexpr int D = 32;
constexpr int ROWS = 4;    // h-rows per CTA
constexpr int PADQ = 72;   // float4s per padded row buffer
}

__device__ __forceinline__ void stcs128(float* p, float4 v) {
    __stcs(reinterpret_cast<float4*>(p), v);
}

__global__ __launch_bounds__(1024)
void cost_volume_kernel(const float* __restrict__ left,
                        const float* __restrict__ right,
                        float* __restrict__ out) {
    // Per row r (0..3):
    //   slbuf[r] floats: [0..255] = left row, [256..287] = zero tail.
    //   srbuf[r] floats: [0..31] = zero head, [32..287] = right row
    //                    (srbuf float j holds right_row[j-32]).
    __shared__ float4 slbuf[ROWS][PADQ];
    __shared__ float4 srbuf[ROWS][PADQ];

    const int blk = blockIdx.x;            // b*C*(H/4) + c*(H/4) + hq
    const int hq = blk & (H / ROWS - 1);   // 32 row-quads per (b,c)
    const int c  = (blk >> 5) & (C - 1);
    const int b  = blk >> 10;

    const int tid   = threadIdx.x;         // 0..1023
    const int rsub  = tid >> 8;            // row within quad (0..3)
    const int t256  = tid & 255;
    const int half  = t256 >> 7;           // 0 = left, 1 = right
    const int dhalf = (t256 >> 6) & 1;     // d block
    const int l64   = t256 & 63;           // float4 column
    const int w4    = l64 << 2;
    const int d0    = dhalf << 4;          // 0 or 16
    const int h     = hq * ROWS + rsub;

    const size_t in_off = ((((size_t)b * C + c) * H) + h) * W;

    // ---- stage 4 row pairs + zero pads (per 256-thread row group) ----
    if (t256 < 64) {
        slbuf[rsub][t256] = reinterpret_cast<const float4*>(left + in_off)[t256];
    } else if (t256 < 128) {
        srbuf[rsub][8 + (t256 - 64)] =
            reinterpret_cast<const float4*>(right + in_off)[t256 - 64];
    } else if (t256 < 136) {
        slbuf[rsub][64 + (t256 - 128)] = make_float4(0.f, 0.f, 0.f, 0.f);
    } else if (t256 < 144) {
        srbuf[rsub][t256 - 136] = make_float4(0.f, 0.f, 0.f, 0.f);
    }
    __syncthreads();

    // ---- 20-float register window (5 x LDS.128) ----
    // Left  thread: f[k] = left_row [w4 + d0 + k],      k = 0..19
    // Right thread: f[k] = right_row[w4 - d0 - 16 + k], k = 0..19
    float f[20];
    {
        const float4* buf  = half ? srbuf[rsub] : slbuf[rsub];
        const int     base = half ? (l64 + 4 - 4 * dhalf) : (l64 + 4 * dhalf);
        #pragma unroll
        for (int i = 0; i < 5; i++) {
            float4 q = buf[base + i];
            f[4 * i + 0] = q.x;
            f[4 * i + 1] = q.y;
            f[4 * i + 2] = q.z;
            f[4 * i + 3] = q.w;
        }
    }

    // ---- emit 16 disparity planes (one uninterrupted streaming burst) ----
    const size_t dstride = (size_t)H * W;  // 32768 floats per d-plane
    float* dst = out
        + ((size_t)(b * 2 * C + half * C + c) * D + d0) * dstride
        + (size_t)h * W + w4;

    if (half == 0) {
        // d = d0 + dd: out = left_row[w4+d .. w4+d+3] = f[dd .. dd+3]
        #pragma unroll
        for (int dd = 0; dd < 16; dd++) {
            float4 v = make_float4(f[dd], f[dd + 1], f[dd + 2], f[dd + 3]);
            stcs128(dst + (size_t)dd * dstride, v);
        }
    } else {
        // d = d0 + dd: out = right_row[w4-d .. w4-d+3] = f[16-dd .. 19-dd]
        #pragma unroll
        for (int dd = 0; dd < 16; dd++) {
            float4 v = make_float4(f[16 - dd], f[17 - dd], f[18 - dd], f[19 - dd]);
            stcs128(dst + (size_t)dd * dstride, v);
        }
    }
}

extern "C" void kernel_launch(void* const* d_in, const int* in_sizes, int n_in,
                              void* d_out, int out_size) {
    const float* left  = (const float*)d_in[0];
    const float* right = (const float*)d_in[1];
    float* out = (float*)d_out;

    (void)in_sizes; (void)n_in; (void)out_size;

    const int grid = B * C * (H / ROWS);  // 2048 CTAs
    cost_volume_kernel<<<grid, 1024>>>(left, right, out);
}

// round 15
// speedup vs baseline: 1.0045x; 1.0045x over previous
#include <cuda_runtime.h>

// CostVolume: left,right [B,C,H,W] f32 -> out [B,2C,D,H,W] f32
//   out[b, c,      d, h, w] = (w+d < W) ? left [b,c,h,w+d] : 0
//   out[b, C + c,  d, h, w] = (w-d >= 0)? right[b,c,h,w-d] : 0
//
// Fixed shapes: B=2, C=32, H=128, W=256, D=32.
//
// FINAL CONVERGED KERNEL (best 76.3us, mean ~77.5us; ~7.15 TB/s effective
// = ~89% of HBM3e spec on the irreducible 537 MB write-once stream).
// Design matrix fully measured over 14 rounds:
//   - One 512-thread CTA per pair of adjacent h rows (grid 4096).
//   - Rows staged once in zero-padded smem (pads encode boundary zeros:
//     store path has no conditionals).
//   - Each thread: 20-float register window (5 x LDS.128) covering its
//     4-float output column across its 16 disparities, then ONE
//     uninterrupted burst of 16 x STG.128 via st.global.cs (evict-first:
//     keeps L2 write aggregation, avoids dirty-line retention).
//   - Measured dead ends: .wt (+8us), STG.256 (+8us octet rebuilds),
//     1-row (+1.5us), 4-row pure-burst (+2us) and 4-row interleaved (+6us),
//     syncless LDG windows (neutral), occ sweep 41-69% (DRAM% flat =>
//     HBM write path is the hard external ceiling).

namespace {
constexpr int B = 2;
constexpr int C = 32;
constexpr int H = 128;
constexpr int W = 256;
constexpr int D = 32;
constexpr int PADQ = 72;   // float4s per padded row buffer
}

__device__ __forceinline__ void stcs128(float* p, float4 v) {
    __stcs(reinterpret_cast<float4*>(p), v);
}

__global__ __launch_bounds__(512)
void cost_volume_kernel(const float* __restrict__ left,
                        const float* __restrict__ right,
                        float* __restrict__ out) {
    // Per row r (0..1):
    //   slbuf[r] floats: [0..255] = left row, [256..287] = zero tail.
    //   srbuf[r] floats: [0..31] = zero head, [32..287] = right row
    //                    (srbuf float j holds right_row[j-32]).
    __shared__ float4 slbuf[2][PADQ];
    __shared__ float4 srbuf[2][PADQ];

    const int blk = blockIdx.x;            // b*C*(H/2) + c*(H/2) + hp
    const int hp = blk & (H / 2 - 1);      // 64 row pairs per (b,c)
    const int c  = (blk >> 6) & (C - 1);
    const int b  = blk >> 11;

    const int tid   = threadIdx.x;         // 0..511
    const int rsub  = tid >> 8;            // row within pair
    const int t256  = tid & 255;
    const int half  = t256 >> 7;           // 0 = left, 1 = right
    const int dhalf = (t256 >> 6) & 1;     // d block
    const int l64   = t256 & 63;           // float4 column
    const int w4    = l64 << 2;
    const int d0    = dhalf << 4;          // 0 or 16
    const int h     = hp * 2 + rsub;

    const size_t in_off = ((((size_t)b * C + c) * H) + h) * W;

    // ---- stage row pair + zero pads (per 256-thread group) ----
    if (t256 < 64) {
        slbuf[rsub][t256] = reinterpret_cast<const float4*>(left + in_off)[t256];
    } else if (t256 < 128) {
        srbuf[rsub][8 + (t256 - 64)] =
            reinterpret_cast<const float4*>(right + in_off)[t256 - 64];
    } else if (t256 < 136) {
        slbuf[rsub][64 + (t256 - 128)] = make_float4(0.f, 0.f, 0.f, 0.f);
    } else if (t256 < 144) {
        srbuf[rsub][t256 - 136] = make_float4(0.f, 0.f, 0.f, 0.f);
    }
    __syncthreads();

    // ---- 20-float register window (5 x LDS.128) ----
    // Left  thread: f[k] = left_row [w4 + d0 + k],      k = 0..19
    // Right thread: f[k] = right_row[w4 - d0 - 16 + k], k = 0..19
    float f[20];
    {
        const float4* buf  = half ? srbuf[rsub] : slbuf[rsub];
        const int     base = half ? (l64 + 4 - 4 * dhalf) : (l64 + 4 * dhalf);
        #pragma unroll
        for (int i = 0; i < 5; i++) {
            float4 q = buf[base + i];
            f[4 * i + 0] = q.x;
            f[4 * i + 1] = q.y;
            f[4 * i + 2] = q.z;
            f[4 * i + 3] = q.w;
        }
    }

    // ---- emit 16 disparity planes (one uninterrupted streaming burst) ----
    const size_t dstride = (size_t)H * W;  // 32768 floats per d-plane
    float* dst = out
        + ((size_t)(b * 2 * C + half * C + c) * D + d0) * dstride
        + (size_t)h * W + w4;

    if (half == 0) {
        // d = d0 + dd: out = left_row[w4+d .. w4+d+3] = f[dd .. dd+3]
        #pragma unroll
        for (int dd = 0; dd < 16; dd++) {
            float4 v = make_float4(f[dd], f[dd + 1], f[dd + 2], f[dd + 3]);
            stcs128(dst + (size_t)dd * dstride, v);
        }
    } else {
        // d = d0 + dd: out = right_row[w4-d .. w4-d+3] = f[16-dd .. 19-dd]
        #pragma unroll
        for (int dd = 0; dd < 16; dd++) {
            float4 v = make_float4(f[16 - dd], f[17 - dd], f[18 - dd], f[19 - dd]);
            stcs128(dst + (size_t)dd * dstride, v);
        }
    }
}

extern "C" void kernel_launch(void* const* d_in, const int* in_sizes, int n_in,
                              void* d_out, int out_size) {
    const float* left  = (const float*)d_in[0];
    const float* right = (const float*)d_in[1];
    float* out = (float*)d_out;

    (void)in_sizes; (void)n_in; (void)out_size;

    const int grid = B * C * (H / 2);  // 4096 CTAs
    cost_volume_kernel<<<grid, 512>>>(left, right, out);
}